// round 16
// baseline (speedup 1.0000x reference)
#include <cuda_runtime.h>
#include <cuda_fp16.h>
#include <math.h>
#include <stdint.h>

// Problem constants
#define S_LEN 2048
#define BATCH 2
#define DMODEL 512
#define NHEAD 8
#define HDIM 64
#define FFDIM 2048
#define NTOK (S_LEN * BATCH)   // 4096
#define WWIN 5
#define LN_EPS 1e-5f

// ---------------- scratch (no allocations allowed) ----------------
__device__ float g_qkv[(size_t)NTOK * 3 * DMODEL];       // self Q|K|V fp32
__device__ float g_kv[(size_t)NTOK * 2 * DMODEL];        // cross K|V fp32
__device__ float g_qc[(size_t)NTOK * DMODEL];            // cross Q fp32
__device__ float g_part[2 * (size_t)NTOK * DMODEL];      // split-K partials
__device__ float g_x1[(size_t)NTOK * DMODEL];
__device__ float g_x2[(size_t)NTOK * DMODEL];
// fp16 GEMM inputs
__device__ __half g_wh[4194304];                         // all weights fp16
__device__ __half g_xh[(size_t)NTOK * DMODEL];
__device__ __half g_ench[(size_t)NTOK * DMODEL];
__device__ __half g_x1h[(size_t)NTOK * DMODEL];
__device__ __half g_x2h[(size_t)NTOK * DMODEL];
__device__ __half g_attnh[(size_t)NTOK * DMODEL];
__device__ __half g_ffh[(size_t)NTOK * FFDIM];
// concatenated biases (fp32)
__device__ float g_bsa[3 * DMODEL];
__device__ float g_bca[2 * DMODEL];

// epilogue flags
#define EF_RELU   1
#define EF_F16OUT 2
#define EF_PAIR   4

// ---------------- convert/copy kernel ----------------
#define NCVT 17
struct CvtArgs {
    const float* src[NCVT];
    void* dst[NCVT];
    int n4[NCVT];     // element count / 4
    int tof[NCVT];    // 1 -> fp32->fp16, 0 -> fp32 copy
};

__global__ __launch_bounds__(256) void cvt_kernel(CvtArgs args) {
    const int ti = blockIdx.y;
    const int n4 = args.n4[ti];
    const int tof = args.tof[ti];
    const float4* src = (const float4*)args.src[ti];
    for (int i = blockIdx.x * 256 + threadIdx.x; i < n4; i += gridDim.x * 256) {
        float4 v = src[i];
        if (tof) {
            __half2* d = (__half2*)args.dst[ti];
            d[2 * i]     = __half2(__float2half_rn(v.x), __float2half_rn(v.y));
            d[2 * i + 1] = __half2(__float2half_rn(v.z), __float2half_rn(v.w));
        } else {
            ((float4*)args.dst[ti])[i] = v;
        }
    }
}

// ---------------- fp16 tensor-core GEMM, BM=BN=128, BK=32, 3-stage + ldmatrix --------
// C[m,n] = sum_k A[m,k]*Bw[n,k] (+bias[n]).  128x128 block tile, 256 threads,
// 8 warps (4M x 2N), warp tile 32x64 via mma.m16n8k16.f16 (fp32 acc), ldmatrix.x4.
// Modes:
//  - EF_PAIR: gridDim.z==2 dispatches two independent GEMMs (z=0: primary,
//    z=1: secondary A2/B2/bias2/C2 with N2; excess column blocks exit).
//  - else gridDim.z = split-K count; z-th K-slice -> partial at C + z*M*N.
#define GBM 128
#define GBN 128
#define GBK 32
#define APADB 40                        // fp16 per smem row (80B: LDSM conflict-free)
#define A_ELE (GBM * APADB)             // 5120
#define B_ELE (GBN * APADB)             // 5120
#define A_BYTES (A_ELE * 2)             // 10240
#define STAGE_BYTES ((A_ELE + B_ELE) * 2)   // 20480
#define NSTAGE 3
#define GEMM_SMEM_BYTES (NSTAGE * STAGE_BYTES)   // 61440

__device__ __forceinline__ void cp16(void* dst, const void* src) {
    uint32_t d = (uint32_t)__cvta_generic_to_shared(dst);
    asm volatile("cp.async.cg.shared.global [%0], [%1], 16;" :: "r"(d), "l"(src));
}

__device__ __forceinline__ void ldsm_x4(uint32_t* r, uint32_t addr) {
    asm volatile("ldmatrix.sync.aligned.m8n8.x4.shared.b16 {%0,%1,%2,%3}, [%4];"
        : "=r"(r[0]), "=r"(r[1]), "=r"(r[2]), "=r"(r[3]) : "r"(addr));
}

__device__ __forceinline__ void mma_f16(float* d, const uint32_t* a, const uint32_t* b) {
    asm volatile(
        "mma.sync.aligned.m16n8k16.row.col.f32.f16.f16.f32 "
        "{%0,%1,%2,%3},{%4,%5,%6,%7},{%8,%9},{%0,%1,%2,%3};"
        : "+f"(d[0]), "+f"(d[1]), "+f"(d[2]), "+f"(d[3])
        : "r"(a[0]), "r"(a[1]), "r"(a[2]), "r"(a[3]), "r"(b[0]), "r"(b[1]));
}

__global__ __launch_bounds__(256) void gemm_f16_kernel(
    const __half* __restrict__ A, const __half* __restrict__ Bw,
    const float* __restrict__ bias,
    float* __restrict__ C, int M, int N, int K, int flags,
    const __half* __restrict__ A2, const __half* __restrict__ B2,
    const float* __restrict__ bias2, float* __restrict__ C2, int N2)
{
    extern __shared__ __half smem[];
    const uint32_t sbase = (uint32_t)__cvta_generic_to_shared(smem);

    // dispatch: pair mode vs split-K mode
    const __half* Ap = A;
    const __half* Bp = Bw;
    const float* bp = bias;
    float* Cp = C;
    int Np = N;
    int Kfull = K;
    int koff = 0;
    if (flags & EF_PAIR) {
        if (blockIdx.z == 1) {
            if ((int)blockIdx.x * GBN >= N2) return;
            Ap = A2; Bp = B2; bp = bias2; Cp = C2; Np = N2;
        }
    } else {
        Kfull = K * gridDim.z;
        koff = blockIdx.z * K;
        Cp = C + (size_t)blockIdx.z * M * N;
    }

    const int t = threadIdx.x;
    const int lane = t & 31;
    const int warp = t >> 5;
    const int wm = warp >> 1;        // 0..3 (32-row slices)
    const int wn = warp & 1;         // 0..1 (64-col slices)
    const int r = lane >> 2;         // 0..7
    const int c = lane & 3;          // 0..3

    const int bm = blockIdx.y * GBM;
    const int bn = blockIdx.x * GBN;

    // cp.async load mapping (fp16 units): A and B both 128 rows x 32 halves,
    // 2 threads/row, 16 halves (1x16B) each -> 2 cp16 per thread per matrix.
    const int lrow = t >> 1;
    const int lhalf = (t & 1) * 16;

    const __half* Abase = Ap + (size_t)(bm + lrow) * Kfull + koff + lhalf;
    const __half* Bbase = Bp + (size_t)(bn + lrow) * Kfull + koff + lhalf;
    const int aoff = lrow * APADB + lhalf;
    const int boff = A_ELE + lrow * APADB + lhalf;

    // ldmatrix per-thread address components (bytes within stage)
    const uint32_t a_off = (uint32_t)(((wm * 32 + (lane & 15)) * APADB + ((lane & 16) >> 1)) * 2);
    const uint32_t b_off = (uint32_t)(A_BYTES +
        ((wn * 64 + (lane & 7) + ((lane & 16) >> 1)) * APADB + (lane & 8)) * 2);

    float acc[2][8][4];
#pragma unroll
    for (int i = 0; i < 2; i++)
#pragma unroll
        for (int j = 0; j < 8; j++)
#pragma unroll
            for (int l = 0; l < 4; l++) acc[i][j][l] = 0.f;

    const int TK = K >> 5;

    // prologue: fill stages 0..1
#pragma unroll
    for (int s = 0; s < NSTAGE - 1; s++) {
        __half* st = smem + s * (A_ELE + B_ELE);
        const int ko = s * GBK;
        cp16(st + aoff, Abase + ko);
        cp16(st + aoff + 8, Abase + ko + 8);
        cp16(st + boff, Bbase + ko);
        cp16(st + boff + 8, Bbase + ko + 8);
        asm volatile("cp.async.commit_group;");
    }

    for (int kt = 0; kt < TK; kt++) {
        // commits so far = kt + 2; wait<=1 -> stage kt ready
        asm volatile("cp.async.wait_group 1;");
        __syncthreads();

        // prefetch stage kt+2 into ring slot (kt+2)%3 (consumed last at iter kt-1)
        if (kt + NSTAGE - 1 < TK) {
            const int slot = (kt + NSTAGE - 1) % NSTAGE;
            __half* st = smem + slot * (A_ELE + B_ELE);
            const int ko = (kt + NSTAGE - 1) * GBK;
            cp16(st + aoff, Abase + ko);
            cp16(st + aoff + 8, Abase + ko + 8);
            cp16(st + boff, Bbase + ko);
            cp16(st + boff + 8, Bbase + ko + 8);
        }
        asm volatile("cp.async.commit_group;");   // always commit (may be empty)

        const uint32_t sa = sbase + (uint32_t)((kt % NSTAGE) * STAGE_BYTES);
        const uint32_t aaddr = sa + a_off;
        const uint32_t baddr = sa + b_off;

#pragma unroll
        for (int ks = 0; ks < 2; ks++) {
            const uint32_t kb = ks * 32;   // 16 fp16 = 32 bytes
            uint32_t a0[4], a1[4];
            uint32_t b0[4], b1[4], b2[4], b3[4];
            ldsm_x4(a0, aaddr + kb);            // m rows wm*32+0..15
            ldsm_x4(a1, aaddr + kb + 1280);     // m rows +16..31 (16*80B)
            ldsm_x4(b0, baddr + kb);            // n +0..15
            ldsm_x4(b1, baddr + kb + 1280);     // n +16..31
            ldsm_x4(b2, baddr + kb + 2560);     // n +32..47
            ldsm_x4(b3, baddr + kb + 3840);     // n +48..63
            mma_f16(acc[0][0], a0, b0);  mma_f16(acc[0][1], a0, b0 + 2);
            mma_f16(acc[0][2], a0, b1);  mma_f16(acc[0][3], a0, b1 + 2);
            mma_f16(acc[0][4], a0, b2);  mma_f16(acc[0][5], a0, b2 + 2);
            mma_f16(acc[0][6], a0, b3);  mma_f16(acc[0][7], a0, b3 + 2);
            mma_f16(acc[1][0], a1, b0);  mma_f16(acc[1][1], a1, b0 + 2);
            mma_f16(acc[1][2], a1, b1);  mma_f16(acc[1][3], a1, b1 + 2);
            mma_f16(acc[1][4], a1, b2);  mma_f16(acc[1][5], a1, b2 + 2);
            mma_f16(acc[1][6], a1, b3);  mma_f16(acc[1][7], a1, b3 + 2);
        }
    }

    // epilogue
#pragma unroll
    for (int mt = 0; mt < 2; mt++) {
        const int m0 = bm + wm * 32 + mt * 16 + r;
#pragma unroll
        for (int nt = 0; nt < 8; nt++) {
            const int n0 = bn + wn * 64 + nt * 8 + c * 2;
#pragma unroll
            for (int e = 0; e < 4; e++) {
                const int m = m0 + (e >> 1) * 8;
                const int n = n0 + (e & 1);
                float v = acc[mt][nt][e];
                if (bp) v += bp[n];
                if (flags & EF_RELU) v = fmaxf(v, 0.f);
                if (flags & EF_F16OUT)
                    ((__half*)Cp)[(size_t)m * Np + n] = __float2half_rn(v);
                else
                    Cp[(size_t)m * Np + n] = v;
            }
        }
    }
}

// ---------------- sparse attention, 8 threads per query (4 dims x 2 key-halves) ------
// Token-row layout: row(tok s, batch b) = s*2+b. Head h at cols [h*64, h*64+64).
// allowed(j|i) = |j-i| <= 5  OR  j % 10 == 0. fixed-max softmax (scores bounded).
// Key loop split across 2 thread halves; fixed-max softmax makes the merge a sum.
#define AQ_PER_BLOCK 32
#define STRIDED_KEYS 205
#define KTILE 32

__global__ __launch_bounds__(256) void attn8_kernel(
    const float* __restrict__ Qb, int ldq,
    const float* __restrict__ Kb, const float* __restrict__ Vb, int ldk,
    __half* __restrict__ O)
{
    __shared__ float sK[KTILE * 64];
    __shared__ float sV[KTILE * 64];

    const int t = threadIdx.x;
    const int lane = t & 31;
    const int bh = blockIdx.y;
    const int b = bh >> 3;
    const int h = bh & 7;
    const int hcol = h * HDIM;
    const int qi = blockIdx.x * AQ_PER_BLOCK + (t >> 3);
    const int dimbase = (lane & 3) * 16;
    const int kh = (lane >> 2) & 1;                    // key half
    const unsigned gmask = 0xFu << (lane & 28);        // 4-lane dim group mask

    float4 q[4];
    const float4* qp = (const float4*)(Qb + (size_t)(qi * BATCH + b) * ldq + hcol + dimbase);
#pragma unroll
    for (int f = 0; f < 4; f++) q[f] = qp[f];

    float4 acc[4];
#pragma unroll
    for (int f = 0; f < 4; f++) acc[f] = make_float4(0.f, 0.f, 0.f, 0.f);
    float lsum = 0.f;

    // ---- strided keys via smem tiles; each key-half scans half the tile ----
    for (int cb = 0; cb < STRIDED_KEYS; cb += KTILE) {
        const int cnt = min(KTILE, STRIDED_KEYS - cb);
        __syncthreads();
        for (int idx = t; idx < cnt * 16; idx += 256) {
            const int kk = idx >> 4;
            const int f4 = idx & 15;
            const int j = (cb + kk) * 10;
            const size_t row = (size_t)(j * BATCH + b) * ldk + hcol;
            ((float4*)sK)[kk * 16 + f4] = ((const float4*)(Kb + row))[f4];
            ((float4*)sV)[kk * 16 + f4] = ((const float4*)(Vb + row))[f4];
        }
        __syncthreads();
        const int klo = kh * 16;
        const int khi = min(cnt, klo + 16);
        for (int kk = klo; kk < khi; kk++) {
            const float4* kp = (const float4*)(sK + kk * 64 + dimbase);
            float p = 0.f;
#pragma unroll
            for (int f = 0; f < 4; f++) {
                float4 kv = kp[f];
                p += q[f].x * kv.x + q[f].y * kv.y + q[f].z * kv.z + q[f].w * kv.w;
            }
            p += __shfl_xor_sync(gmask, p, 1);
            p += __shfl_xor_sync(gmask, p, 2);
            const float e = __expf(p * 0.125f);
            lsum += e;
            const float4* vp = (const float4*)(sV + kk * 64 + dimbase);
#pragma unroll
            for (int f = 0; f < 4; f++) {
                float4 vv = vp[f];
                acc[f].x += e * vv.x; acc[f].y += e * vv.y;
                acc[f].z += e * vv.z; acc[f].w += e * vv.w;
            }
        }
    }

    // ---- band keys (|j - i| <= 5, excluding j % 10 == 0), split by key-half ----
    const int djlo = kh ? 1 : -WWIN;
    const int djhi = kh ? WWIN : 0;
    for (int dj = djlo; dj <= djhi; dj++) {
        const int j = qi + dj;
        const bool valid = (j >= 0) && (j < S_LEN) && (j % 10 != 0);
        const int jc = min(max(j, 0), S_LEN - 1);
        const size_t row = (size_t)(jc * BATCH + b) * ldk + hcol + dimbase;
        const float4* kp = (const float4*)(Kb + row);
        float p = 0.f;
#pragma unroll
        for (int f = 0; f < 4; f++) {
            float4 kv = kp[f];
            p += q[f].x * kv.x + q[f].y * kv.y + q[f].z * kv.z + q[f].w * kv.w;
        }
        p += __shfl_xor_sync(gmask, p, 1);
        p += __shfl_xor_sync(gmask, p, 2);
        const float e = valid ? __expf(p * 0.125f) : 0.f;
        lsum += e;
        const float4* vp = (const float4*)(Vb + row);
#pragma unroll
        for (int f = 0; f < 4; f++) {
            float4 vv = vp[f];
            acc[f].x += e * vv.x; acc[f].y += e * vv.y;
            acc[f].z += e * vv.z; acc[f].w += e * vv.w;
        }
    }

    // ---- merge the two key-halves (sum; fixed-max softmax) ----
    __syncwarp();
    lsum += __shfl_xor_sync(0xffffffffu, lsum, 4);
#pragma unroll
    for (int f = 0; f < 4; f++) {
        acc[f].x += __shfl_xor_sync(0xffffffffu, acc[f].x, 4);
        acc[f].y += __shfl_xor_sync(0xffffffffu, acc[f].y, 4);
        acc[f].z += __shfl_xor_sync(0xffffffffu, acc[f].z, 4);
        acc[f].w += __shfl_xor_sync(0xffffffffu, acc[f].w, 4);
    }

    if (kh == 0) {
        const float inv = 1.f / lsum;
        __half2* op = (__half2*)(O + (size_t)(qi * BATCH + b) * DMODEL + hcol + dimbase);
#pragma unroll
        for (int f = 0; f < 4; f++) {
            op[2 * f]     = __half2(__float2half_rn(acc[f].x * inv),
                                    __float2half_rn(acc[f].y * inv));
            op[2 * f + 1] = __half2(__float2half_rn(acc[f].z * inv),
                                    __float2half_rn(acc[f].w * inv));
        }
    }
}

// ---------------- ln_sum: sum partials + bias + residual, LN, dual fp32/fp16 out ----------------
__global__ __launch_bounds__(128) void ln_sum_kernel(
    const float* __restrict__ parts, int nsplit,
    const float* __restrict__ bias, const float* __restrict__ res,
    const float* __restrict__ g, const float* __restrict__ b,
    float* __restrict__ out, __half* __restrict__ out_h)
{
    const int row = blockIdx.x;
    const int t = threadIdx.x;
    const size_t pstride = (size_t)NTOK * DMODEL;
    const size_t off = (size_t)row * DMODEL;

    float4 v = ((const float4*)(parts + off))[t];
    if (nsplit == 2) {
        float4 p = ((const float4*)(parts + pstride + off))[t];
        v.x += p.x; v.y += p.y; v.z += p.z; v.w += p.w;
    }
    const float4 bi = ((const float4*)bias)[t];
    const float4 rr = ((const float4*)(res + off))[t];
    v.x += bi.x + rr.x; v.y += bi.y + rr.y;
    v.z += bi.z + rr.z; v.w += bi.w + rr.w;

    float s  = v.x + v.y + v.z + v.w;
    float ss = v.x * v.x + v.y * v.y + v.z * v.z + v.w * v.w;
#pragma unroll
    for (int o2 = 16; o2; o2 >>= 1) {
        s  += __shfl_xor_sync(0xffffffffu, s, o2);
        ss += __shfl_xor_sync(0xffffffffu, ss, o2);
    }
    __shared__ float red[8];
    const int wid = t >> 5;
    if ((t & 31) == 0) { red[wid] = s; red[4 + wid] = ss; }
    __syncthreads();
    s  = red[0] + red[1] + red[2] + red[3];
    ss = red[4] + red[5] + red[6] + red[7];

    const float mean = s * (1.f / DMODEL);
    const float var  = ss * (1.f / DMODEL) - mean * mean;
    const float rs = rsqrtf(var + LN_EPS);

    const float4 gg = ((const float4*)g)[t];
    const float4 bb = ((const float4*)b)[t];
    float4 o;
    o.x = (v.x - mean) * rs * gg.x + bb.x;
    o.y = (v.y - mean) * rs * gg.y + bb.y;
    o.z = (v.z - mean) * rs * gg.z + bb.z;
    o.w = (v.w - mean) * rs * gg.w + bb.w;
    ((float4*)(out + off))[t] = o;
    if (out_h) {
        __half2* d = (__half2*)(out_h + off);
        d[2 * t]     = __half2(__float2half_rn(o.x), __float2half_rn(o.y));
        d[2 * t + 1] = __half2(__float2half_rn(o.z), __float2half_rn(o.w));
    }
}

// ---------------- launch ----------------
extern "C" void kernel_launch(void* const* d_in, const int* in_sizes, int n_in,
                              void* d_out, int out_size)
{
    const float* x   = (const float*)d_in[0];
    const float* enc = (const float*)d_in[1];
    const float* sa_Wq = (const float*)d_in[2];
    const float* sa_Wk = (const float*)d_in[3];
    const float* sa_Wv = (const float*)d_in[4];
    const float* sa_Wo = (const float*)d_in[5];
    const float* sa_bq = (const float*)d_in[6];
    const float* sa_bk = (const float*)d_in[7];
    const float* sa_bv = (const float*)d_in[8];
    const float* sa_bo = (const float*)d_in[9];
    const float* ca_Wq = (const float*)d_in[10];
    const float* ca_Wk = (const float*)d_in[11];
    const float* ca_Wv = (const float*)d_in[12];
    const float* ca_Wo = (const float*)d_in[13];
    const float* ca_bq = (const float*)d_in[14];
    const float* ca_bk = (const float*)d_in[15];
    const float* ca_bv = (const float*)d_in[16];
    const float* ca_bo = (const float*)d_in[17];
    const float* ff_W1 = (const float*)d_in[18];
    const float* ff_W2 = (const float*)d_in[19];
    const float* ff_b1 = (const float*)d_in[20];
    const float* ff_b2 = (const float*)d_in[21];
    const float* ln1_g = (const float*)d_in[22];
    const float* ln1_b = (const float*)d_in[23];
    const float* ln2_g = (const float*)d_in[24];
    const float* ln2_b = (const float*)d_in[25];
    const float* ln3_g = (const float*)d_in[26];
    const float* ln3_b = (const float*)d_in[27];
    float* out = (float*)d_out;

    float *qkv, *kv, *qc, *part, *x1, *x2, *bsa, *bca;
    __half *wh, *xh, *ench, *x1h, *x2h, *attnh, *ffh;
    cudaGetSymbolAddress((void**)&qkv, g_qkv);
    cudaGetSymbolAddress((void**)&kv, g_kv);
    cudaGetSymbolAddress((void**)&qc, g_qc);
    cudaGetSymbolAddress((void**)&part, g_part);
    cudaGetSymbolAddress((void**)&x1, g_x1);
    cudaGetSymbolAddress((void**)&x2, g_x2);
    cudaGetSymbolAddress((void**)&bsa, g_bsa);
    cudaGetSymbolAddress((void**)&bca, g_bca);
    cudaGetSymbolAddress((void**)&wh, g_wh);
    cudaGetSymbolAddress((void**)&xh, g_xh);
    cudaGetSymbolAddress((void**)&ench, g_ench);
    cudaGetSymbolAddress((void**)&x1h, g_x1h);
    cudaGetSymbolAddress((void**)&x2h, g_x2h);
    cudaGetSymbolAddress((void**)&attnh, g_attnh);
    cudaGetSymbolAddress((void**)&ffh, g_ffh);

    const int PW = DMODEL * DMODEL;
    __half* w_saWqkv = wh + 0 * PW;            // Wq|Wk|Wv contiguous
    __half* w_saWo   = wh + 3 * PW;
    __half* w_caWq   = wh + 4 * PW;
    __half* w_caWkv  = wh + 5 * PW;            // Wk|Wv contiguous
    __half* w_caWo   = wh + 7 * PW;
    __half* w_ffW1   = wh + 8 * PW;
    __half* w_ffW2   = wh + 8 * PW + FFDIM * DMODEL;

    CvtArgs ca;
    const float* srcs[NCVT] = { sa_Wq, sa_Wk, sa_Wv, sa_Wo, ca_Wq, ca_Wk, ca_Wv, ca_Wo,
                                ff_W1, ff_W2, x, enc,
                                sa_bq, sa_bk, sa_bv, ca_bk, ca_bv };
    void* dsts[NCVT] = { w_saWqkv, w_saWqkv + PW, w_saWqkv + 2 * PW, w_saWo,
                         w_caWq, w_caWkv, w_caWkv + PW, w_caWo,
                         w_ffW1, w_ffW2, xh, ench,
                         bsa, bsa + DMODEL, bsa + 2 * DMODEL, bca, bca + DMODEL };
    int ns[NCVT] = { PW, PW, PW, PW, PW, PW, PW, PW,
                     FFDIM * DMODEL, FFDIM * DMODEL, NTOK * DMODEL, NTOK * DMODEL,
                     DMODEL, DMODEL, DMODEL, DMODEL, DMODEL };
    int tof[NCVT] = { 1,1,1,1, 1,1,1,1, 1,1, 1,1, 0,0,0, 0,0 };
    for (int i = 0; i < NCVT; i++) {
        ca.src[i] = srcs[i]; ca.dst[i] = dsts[i]; ca.n4[i] = ns[i] / 4; ca.tof[i] = tof[i];
    }

    cudaFuncSetAttribute(gemm_f16_kernel,
                         cudaFuncAttributeMaxDynamicSharedMemorySize, GEMM_SMEM_BYTES);

    const dim3 gblk(256);
    const dim3 gPair(3 * DMODEL / GBN, NTOK / GBM, 2);   // (12, 32, 2): QKV + cross-KV
    const dim3 gProj(DMODEL / GBN, NTOK / GBM, 1);       // (4, 32) = 128
    const dim3 gProjS2(DMODEL / GBN, NTOK / GBM, 2);     // 256, split-K 2 (K=256/slice)
    const dim3 gFF1(FFDIM / GBN, NTOK / GBM, 1);         // (16, 32) = 512
    const dim3 gFF2S2(DMODEL / GBN, NTOK / GBM, 2);      // 256, split-K 2 (K=1024/slice)
    const dim3 gAttn(S_LEN / AQ_PER_BLOCK, BATCH * NHEAD);  // (64, 16)

    cvt_kernel<<<dim3(128, NCVT), 256>>>(ca);

    // ---- self attention (QKV fused with cross-KV, which only needs enc) ----
    gemm_f16_kernel<<<gPair, gblk, GEMM_SMEM_BYTES>>>(
        xh, w_saWqkv, bsa, qkv, NTOK, 3 * DMODEL, DMODEL, EF_PAIR,
        ench, w_caWkv, bca, kv, 2 * DMODEL);
    attn8_kernel<<<gAttn, 256>>>(qkv, 3 * DMODEL, qkv + DMODEL, qkv + 2 * DMODEL, 3 * DMODEL, attnh);
    gemm_f16_kernel<<<gProjS2, gblk, GEMM_SMEM_BYTES>>>(
        attnh, w_saWo, nullptr, part, NTOK, DMODEL, DMODEL / 2, 0,
        nullptr, nullptr, nullptr, nullptr, 0);
    ln_sum_kernel<<<NTOK, 128>>>(part, 2, sa_bo, x, ln1_g, ln1_b, x1, x1h);

    // ---- cross attention (KV already computed above) ----
    gemm_f16_kernel<<<gProj, gblk, GEMM_SMEM_BYTES>>>(
        x1h, w_caWq, ca_bq, qc, NTOK, DMODEL, DMODEL, 0,
        nullptr, nullptr, nullptr, nullptr, 0);
    attn8_kernel<<<gAttn, 256>>>(qc, DMODEL, kv, kv + DMODEL, 2 * DMODEL, attnh);
    gemm_f16_kernel<<<gProjS2, gblk, GEMM_SMEM_BYTES>>>(
        attnh, w_caWo, nullptr, part, NTOK, DMODEL, DMODEL / 2, 0,
        nullptr, nullptr, nullptr, nullptr, 0);
    ln_sum_kernel<<<NTOK, 128>>>(part, 2, ca_bo, x1, ln2_g, ln2_b, x2, x2h);

    // ---- feed forward ----
    gemm_f16_kernel<<<gFF1, gblk, GEMM_SMEM_BYTES>>>(
        x2h, w_ffW1, ff_b1, (float*)ffh, NTOK, FFDIM, DMODEL, EF_RELU | EF_F16OUT,
        nullptr, nullptr, nullptr, nullptr, 0);
    gemm_f16_kernel<<<gFF2S2, gblk, GEMM_SMEM_BYTES>>>(
        ffh, w_ffW2, nullptr, part, NTOK, DMODEL, FFDIM / 2, 0,
        nullptr, nullptr, nullptr, nullptr, 0);
    ln_sum_kernel<<<NTOK, 128>>>(part, 2, ff_b2, x2, ln3_g, ln3_b, out, nullptr);
}

// round 17
// speedup vs baseline: 1.5648x; 1.5648x over previous
#include <cuda_runtime.h>
#include <cuda_fp16.h>
#include <math.h>
#include <stdint.h>

// Problem constants
#define S_LEN 2048
#define BATCH 2
#define DMODEL 512
#define NHEAD 8
#define HDIM 64
#define FFDIM 2048
#define NTOK (S_LEN * BATCH)   // 4096
#define WWIN 5
#define LN_EPS 1e-5f

// ---------------- scratch (no allocations allowed) ----------------
__device__ float g_qkv[(size_t)NTOK * 3 * DMODEL];       // self Q|K|V fp32
__device__ float g_kv[(size_t)NTOK * 2 * DMODEL];        // cross K|V fp32
__device__ float g_qc[(size_t)NTOK * DMODEL];            // cross Q fp32
__device__ float g_part[2 * (size_t)NTOK * DMODEL];      // split-K partials
__device__ float g_x1[(size_t)NTOK * DMODEL];
__device__ float g_x2[(size_t)NTOK * DMODEL];
// fp16 GEMM inputs
__device__ __half g_wh[4194304];                         // all weights fp16
__device__ __half g_xh[(size_t)NTOK * DMODEL];
__device__ __half g_ench[(size_t)NTOK * DMODEL];
__device__ __half g_x1h[(size_t)NTOK * DMODEL];
__device__ __half g_x2h[(size_t)NTOK * DMODEL];
__device__ __half g_attnh[(size_t)NTOK * DMODEL];
__device__ __half g_ffh[(size_t)NTOK * FFDIM];
// concatenated biases (fp32)
__device__ float g_bsa[3 * DMODEL];
__device__ float g_bca[2 * DMODEL];

// epilogue flags
#define EF_RELU   1
#define EF_F16OUT 2
#define EF_PAIR   4

// ---------------- convert/copy kernel ----------------
#define NCVT 17
struct CvtArgs {
    const float* src[NCVT];
    void* dst[NCVT];
    int n4[NCVT];     // element count / 4
    int tof[NCVT];    // 1 -> fp32->fp16, 0 -> fp32 copy
};

__global__ __launch_bounds__(256) void cvt_kernel(CvtArgs args) {
    const int ti = blockIdx.y;
    const int n4 = args.n4[ti];
    const int tof = args.tof[ti];
    const float4* src = (const float4*)args.src[ti];
    for (int i = blockIdx.x * 256 + threadIdx.x; i < n4; i += gridDim.x * 256) {
        float4 v = src[i];
        if (tof) {
            __half2* d = (__half2*)args.dst[ti];
            d[2 * i]     = __half2(__float2half_rn(v.x), __float2half_rn(v.y));
            d[2 * i + 1] = __half2(__float2half_rn(v.z), __float2half_rn(v.w));
        } else {
            ((float4*)args.dst[ti])[i] = v;
        }
    }
}

// ---------------- fp16 tensor-core GEMM, BM=BN=128, BK=32, 3-stage + ldmatrix --------
// C[m,n] = sum_k A[m,k]*Bw[n,k] (+bias[n]).  128x128 block tile, 256 threads,
// 8 warps (4M x 2N), warp tile 32x64 via mma.m16n8k16.f16 (fp32 acc), ldmatrix.x4.
// Modes:
//  - EF_PAIR: gridDim.z==2 dispatches two independent GEMMs (z=0: primary,
//    z=1: secondary A2/B2/bias2/C2 with N2; excess column blocks exit).
//  - else gridDim.z = split-K count; z-th K-slice -> partial at C + z*M*N.
#define GBM 128
#define GBN 128
#define GBK 32
#define APADB 40                        // fp16 per smem row (80B: LDSM conflict-free)
#define A_ELE (GBM * APADB)             // 5120
#define B_ELE (GBN * APADB)             // 5120
#define A_BYTES (A_ELE * 2)             // 10240
#define STAGE_BYTES ((A_ELE + B_ELE) * 2)   // 20480
#define NSTAGE 3
#define GEMM_SMEM_BYTES (NSTAGE * STAGE_BYTES)   // 61440

__device__ __forceinline__ void cp16(void* dst, const void* src) {
    uint32_t d = (uint32_t)__cvta_generic_to_shared(dst);
    asm volatile("cp.async.cg.shared.global [%0], [%1], 16;" :: "r"(d), "l"(src));
}

__device__ __forceinline__ void ldsm_x4(uint32_t* r, uint32_t addr) {
    asm volatile("ldmatrix.sync.aligned.m8n8.x4.shared.b16 {%0,%1,%2,%3}, [%4];"
        : "=r"(r[0]), "=r"(r[1]), "=r"(r[2]), "=r"(r[3]) : "r"(addr));
}

__device__ __forceinline__ void mma_f16(float* d, const uint32_t* a, const uint32_t* b) {
    asm volatile(
        "mma.sync.aligned.m16n8k16.row.col.f32.f16.f16.f32 "
        "{%0,%1,%2,%3},{%4,%5,%6,%7},{%8,%9},{%0,%1,%2,%3};"
        : "+f"(d[0]), "+f"(d[1]), "+f"(d[2]), "+f"(d[3])
        : "r"(a[0]), "r"(a[1]), "r"(a[2]), "r"(a[3]), "r"(b[0]), "r"(b[1]));
}

__global__ __launch_bounds__(256) void gemm_f16_kernel(
    const __half* __restrict__ A, const __half* __restrict__ Bw,
    const float* __restrict__ bias,
    float* __restrict__ C, int M, int N, int K, int flags,
    const __half* __restrict__ A2, const __half* __restrict__ B2,
    const float* __restrict__ bias2, float* __restrict__ C2, int N2)
{
    extern __shared__ __half smem[];
    const uint32_t sbase = (uint32_t)__cvta_generic_to_shared(smem);

    // dispatch: pair mode vs split-K mode
    const __half* Ap = A;
    const __half* Bp = Bw;
    const float* bp = bias;
    float* Cp = C;
    int Np = N;
    int Kfull = K;
    int koff = 0;
    if (flags & EF_PAIR) {
        if (blockIdx.z == 1) {
            if ((int)blockIdx.x * GBN >= N2) return;
            Ap = A2; Bp = B2; bp = bias2; Cp = C2; Np = N2;
        }
    } else {
        Kfull = K * gridDim.z;
        koff = blockIdx.z * K;
        Cp = C + (size_t)blockIdx.z * M * N;
    }

    const int t = threadIdx.x;
    const int lane = t & 31;
    const int warp = t >> 5;
    const int wm = warp >> 1;        // 0..3 (32-row slices)
    const int wn = warp & 1;         // 0..1 (64-col slices)
    const int r = lane >> 2;         // 0..7
    const int c = lane & 3;          // 0..3

    const int bm = blockIdx.y * GBM;
    const int bn = blockIdx.x * GBN;

    // cp.async load mapping (fp16 units): A and B both 128 rows x 32 halves,
    // 2 threads/row, 16 halves (1x16B) each -> 2 cp16 per thread per matrix.
    const int lrow = t >> 1;
    const int lhalf = (t & 1) * 16;

    const __half* Abase = Ap + (size_t)(bm + lrow) * Kfull + koff + lhalf;
    const __half* Bbase = Bp + (size_t)(bn + lrow) * Kfull + koff + lhalf;
    const int aoff = lrow * APADB + lhalf;
    const int boff = A_ELE + lrow * APADB + lhalf;

    // ldmatrix per-thread address components (bytes within stage)
    const uint32_t a_off = (uint32_t)(((wm * 32 + (lane & 15)) * APADB + ((lane & 16) >> 1)) * 2);
    const uint32_t b_off = (uint32_t)(A_BYTES +
        ((wn * 64 + (lane & 7) + ((lane & 16) >> 1)) * APADB + (lane & 8)) * 2);

    float acc[2][8][4];
#pragma unroll
    for (int i = 0; i < 2; i++)
#pragma unroll
        for (int j = 0; j < 8; j++)
#pragma unroll
            for (int l = 0; l < 4; l++) acc[i][j][l] = 0.f;

    const int TK = K >> 5;

    // prologue: fill stages 0..1
#pragma unroll
    for (int s = 0; s < NSTAGE - 1; s++) {
        __half* st = smem + s * (A_ELE + B_ELE);
        const int ko = s * GBK;
        cp16(st + aoff, Abase + ko);
        cp16(st + aoff + 8, Abase + ko + 8);
        cp16(st + boff, Bbase + ko);
        cp16(st + boff + 8, Bbase + ko + 8);
        asm volatile("cp.async.commit_group;");
    }

    for (int kt = 0; kt < TK; kt++) {
        // commits so far = kt + 2; wait<=1 -> stage kt ready
        asm volatile("cp.async.wait_group 1;");
        __syncthreads();

        // prefetch stage kt+2 into ring slot (kt+2)%3 (consumed last at iter kt-1)
        if (kt + NSTAGE - 1 < TK) {
            const int slot = (kt + NSTAGE - 1) % NSTAGE;
            __half* st = smem + slot * (A_ELE + B_ELE);
            const int ko = (kt + NSTAGE - 1) * GBK;
            cp16(st + aoff, Abase + ko);
            cp16(st + aoff + 8, Abase + ko + 8);
            cp16(st + boff, Bbase + ko);
            cp16(st + boff + 8, Bbase + ko + 8);
        }
        asm volatile("cp.async.commit_group;");   // always commit (may be empty)

        const uint32_t sa = sbase + (uint32_t)((kt % NSTAGE) * STAGE_BYTES);
        const uint32_t aaddr = sa + a_off;
        const uint32_t baddr = sa + b_off;

#pragma unroll
        for (int ks = 0; ks < 2; ks++) {
            const uint32_t kb = ks * 32;   // 16 fp16 = 32 bytes
            uint32_t a0[4], a1[4];
            uint32_t b0[4], b1[4], b2[4], b3[4];
            ldsm_x4(a0, aaddr + kb);            // m rows wm*32+0..15
            ldsm_x4(a1, aaddr + kb + 1280);     // m rows +16..31 (16*80B)
            ldsm_x4(b0, baddr + kb);            // n +0..15
            ldsm_x4(b1, baddr + kb + 1280);     // n +16..31
            ldsm_x4(b2, baddr + kb + 2560);     // n +32..47
            ldsm_x4(b3, baddr + kb + 3840);     // n +48..63
            mma_f16(acc[0][0], a0, b0);  mma_f16(acc[0][1], a0, b0 + 2);
            mma_f16(acc[0][2], a0, b1);  mma_f16(acc[0][3], a0, b1 + 2);
            mma_f16(acc[0][4], a0, b2);  mma_f16(acc[0][5], a0, b2 + 2);
            mma_f16(acc[0][6], a0, b3);  mma_f16(acc[0][7], a0, b3 + 2);
            mma_f16(acc[1][0], a1, b0);  mma_f16(acc[1][1], a1, b0 + 2);
            mma_f16(acc[1][2], a1, b1);  mma_f16(acc[1][3], a1, b1 + 2);
            mma_f16(acc[1][4], a1, b2);  mma_f16(acc[1][5], a1, b2 + 2);
            mma_f16(acc[1][6], a1, b3);  mma_f16(acc[1][7], a1, b3 + 2);
        }
    }

    // epilogue
#pragma unroll
    for (int mt = 0; mt < 2; mt++) {
        const int m0 = bm + wm * 32 + mt * 16 + r;
#pragma unroll
        for (int nt = 0; nt < 8; nt++) {
            const int n0 = bn + wn * 64 + nt * 8 + c * 2;
#pragma unroll
            for (int e = 0; e < 4; e++) {
                const int m = m0 + (e >> 1) * 8;
                const int n = n0 + (e & 1);
                float v = acc[mt][nt][e];
                if (bp) v += bp[n];
                if (flags & EF_RELU) v = fmaxf(v, 0.f);
                if (flags & EF_F16OUT)
                    ((__half*)Cp)[(size_t)m * Np + n] = __float2half_rn(v);
                else
                    Cp[(size_t)m * Np + n] = v;
            }
        }
    }
}

// ---------------- sparse attention, 4 threads per query, 128 queries/block ----------
// Token-row layout: row(tok s, batch b) = s*2+b. Head h at cols [h*64, h*64+64).
// allowed(j|i) = |j-i| <= 5  OR  j % 10 == 0. fixed-max softmax (scores bounded).
// 512 threads: strided K/V tiles amortized across 2x more queries per block.
#define AQ_PER_BLOCK 128
#define STRIDED_KEYS 205
#define KTILE 32

__global__ __launch_bounds__(512) void attn4_kernel(
    const float* __restrict__ Qb, int ldq,
    const float* __restrict__ Kb, const float* __restrict__ Vb, int ldk,
    __half* __restrict__ O)
{
    __shared__ float sK[KTILE * 64];
    __shared__ float sV[KTILE * 64];

    const int t = threadIdx.x;
    const int bh = blockIdx.y;
    const int b = bh >> 3;
    const int h = bh & 7;
    const int hcol = h * HDIM;
    const int qi = blockIdx.x * AQ_PER_BLOCK + (t >> 2);
    const int dimbase = (t & 3) * 16;

    float4 q[4];
    const float4* qp = (const float4*)(Qb + (size_t)(qi * BATCH + b) * ldq + hcol + dimbase);
#pragma unroll
    for (int f = 0; f < 4; f++) q[f] = qp[f];

    float4 acc[4];
#pragma unroll
    for (int f = 0; f < 4; f++) acc[f] = make_float4(0.f, 0.f, 0.f, 0.f);
    float lsum = 0.f;

    for (int cb = 0; cb < STRIDED_KEYS; cb += KTILE) {
        const int cnt = min(KTILE, STRIDED_KEYS - cb);
        __syncthreads();
        if (t < cnt * 16) {
            const int kk = t >> 4;
            const int f4 = t & 15;
            const int j = (cb + kk) * 10;
            const size_t row = (size_t)(j * BATCH + b) * ldk + hcol;
            ((float4*)sK)[kk * 16 + f4] = ((const float4*)(Kb + row))[f4];
            ((float4*)sV)[kk * 16 + f4] = ((const float4*)(Vb + row))[f4];
        }
        __syncthreads();
        for (int kk = 0; kk < cnt; kk++) {
            const float4* kp = (const float4*)(sK + kk * 64 + dimbase);
            float p = 0.f;
#pragma unroll
            for (int f = 0; f < 4; f++) {
                float4 kv = kp[f];
                p += q[f].x * kv.x + q[f].y * kv.y + q[f].z * kv.z + q[f].w * kv.w;
            }
            p += __shfl_xor_sync(0xffffffffu, p, 1);
            p += __shfl_xor_sync(0xffffffffu, p, 2);
            const float e = __expf(p * 0.125f);
            lsum += e;
            const float4* vp = (const float4*)(sV + kk * 64 + dimbase);
#pragma unroll
            for (int f = 0; f < 4; f++) {
                float4 vv = vp[f];
                acc[f].x += e * vv.x; acc[f].y += e * vv.y;
                acc[f].z += e * vv.z; acc[f].w += e * vv.w;
            }
        }
    }

#pragma unroll
    for (int dj = -WWIN; dj <= WWIN; dj++) {
        const int j = qi + dj;
        const bool valid = (j >= 0) && (j < S_LEN) && (j % 10 != 0);
        const int jc = min(max(j, 0), S_LEN - 1);
        const size_t row = (size_t)(jc * BATCH + b) * ldk + hcol + dimbase;
        const float4* kp = (const float4*)(Kb + row);
        float p = 0.f;
#pragma unroll
        for (int f = 0; f < 4; f++) {
            float4 kv = kp[f];
            p += q[f].x * kv.x + q[f].y * kv.y + q[f].z * kv.z + q[f].w * kv.w;
        }
        p += __shfl_xor_sync(0xffffffffu, p, 1);
        p += __shfl_xor_sync(0xffffffffu, p, 2);
        const float e = valid ? __expf(p * 0.125f) : 0.f;
        lsum += e;
        const float4* vp = (const float4*)(Vb + row);
#pragma unroll
        for (int f = 0; f < 4; f++) {
            float4 vv = vp[f];
            acc[f].x += e * vv.x; acc[f].y += e * vv.y;
            acc[f].z += e * vv.z; acc[f].w += e * vv.w;
        }
    }

    const float inv = 1.f / lsum;
    __half2* op = (__half2*)(O + (size_t)(qi * BATCH + b) * DMODEL + hcol + dimbase);
#pragma unroll
    for (int f = 0; f < 4; f++) {
        op[2 * f]     = __half2(__float2half_rn(acc[f].x * inv),
                                __float2half_rn(acc[f].y * inv));
        op[2 * f + 1] = __half2(__float2half_rn(acc[f].z * inv),
                                __float2half_rn(acc[f].w * inv));
    }
}

// ---------------- ln_sum: sum partials + bias + residual, LN, dual fp32/fp16 out ----------------
__global__ __launch_bounds__(128) void ln_sum_kernel(
    const float* __restrict__ parts, int nsplit,
    const float* __restrict__ bias, const float* __restrict__ res,
    const float* __restrict__ g, const float* __restrict__ b,
    float* __restrict__ out, __half* __restrict__ out_h)
{
    const int row = blockIdx.x;
    const int t = threadIdx.x;
    const size_t pstride = (size_t)NTOK * DMODEL;
    const size_t off = (size_t)row * DMODEL;

    float4 v = ((const float4*)(parts + off))[t];
    if (nsplit == 2) {
        float4 p = ((const float4*)(parts + pstride + off))[t];
        v.x += p.x; v.y += p.y; v.z += p.z; v.w += p.w;
    }
    const float4 bi = ((const float4*)bias)[t];
    const float4 rr = ((const float4*)(res + off))[t];
    v.x += bi.x + rr.x; v.y += bi.y + rr.y;
    v.z += bi.z + rr.z; v.w += bi.w + rr.w;

    float s  = v.x + v.y + v.z + v.w;
    float ss = v.x * v.x + v.y * v.y + v.z * v.z + v.w * v.w;
#pragma unroll
    for (int o2 = 16; o2; o2 >>= 1) {
        s  += __shfl_xor_sync(0xffffffffu, s, o2);
        ss += __shfl_xor_sync(0xffffffffu, ss, o2);
    }
    __shared__ float red[8];
    const int wid = t >> 5;
    if ((t & 31) == 0) { red[wid] = s; red[4 + wid] = ss; }
    __syncthreads();
    s  = red[0] + red[1] + red[2] + red[3];
    ss = red[4] + red[5] + red[6] + red[7];

    const float mean = s * (1.f / DMODEL);
    const float var  = ss * (1.f / DMODEL) - mean * mean;
    const float rs = rsqrtf(var + LN_EPS);

    const float4 gg = ((const float4*)g)[t];
    const float4 bb = ((const float4*)b)[t];
    float4 o;
    o.x = (v.x - mean) * rs * gg.x + bb.x;
    o.y = (v.y - mean) * rs * gg.y + bb.y;
    o.z = (v.z - mean) * rs * gg.z + bb.z;
    o.w = (v.w - mean) * rs * gg.w + bb.w;
    ((float4*)(out + off))[t] = o;
    if (out_h) {
        __half2* d = (__half2*)(out_h + off);
        d[2 * t]     = __half2(__float2half_rn(o.x), __float2half_rn(o.y));
        d[2 * t + 1] = __half2(__float2half_rn(o.z), __float2half_rn(o.w));
    }
}

// ---------------- launch ----------------
extern "C" void kernel_launch(void* const* d_in, const int* in_sizes, int n_in,
                              void* d_out, int out_size)
{
    const float* x   = (const float*)d_in[0];
    const float* enc = (const float*)d_in[1];
    const float* sa_Wq = (const float*)d_in[2];
    const float* sa_Wk = (const float*)d_in[3];
    const float* sa_Wv = (const float*)d_in[4];
    const float* sa_Wo = (const float*)d_in[5];
    const float* sa_bq = (const float*)d_in[6];
    const float* sa_bk = (const float*)d_in[7];
    const float* sa_bv = (const float*)d_in[8];
    const float* sa_bo = (const float*)d_in[9];
    const float* ca_Wq = (const float*)d_in[10];
    const float* ca_Wk = (const float*)d_in[11];
    const float* ca_Wv = (const float*)d_in[12];
    const float* ca_Wo = (const float*)d_in[13];
    const float* ca_bq = (const float*)d_in[14];
    const float* ca_bk = (const float*)d_in[15];
    const float* ca_bv = (const float*)d_in[16];
    const float* ca_bo = (const float*)d_in[17];
    const float* ff_W1 = (const float*)d_in[18];
    const float* ff_W2 = (const float*)d_in[19];
    const float* ff_b1 = (const float*)d_in[20];
    const float* ff_b2 = (const float*)d_in[21];
    const float* ln1_g = (const float*)d_in[22];
    const float* ln1_b = (const float*)d_in[23];
    const float* ln2_g = (const float*)d_in[24];
    const float* ln2_b = (const float*)d_in[25];
    const float* ln3_g = (const float*)d_in[26];
    const float* ln3_b = (const float*)d_in[27];
    float* out = (float*)d_out;

    float *qkv, *kv, *qc, *part, *x1, *x2, *bsa, *bca;
    __half *wh, *xh, *ench, *x1h, *x2h, *attnh, *ffh;
    cudaGetSymbolAddress((void**)&qkv, g_qkv);
    cudaGetSymbolAddress((void**)&kv, g_kv);
    cudaGetSymbolAddress((void**)&qc, g_qc);
    cudaGetSymbolAddress((void**)&part, g_part);
    cudaGetSymbolAddress((void**)&x1, g_x1);
    cudaGetSymbolAddress((void**)&x2, g_x2);
    cudaGetSymbolAddress((void**)&bsa, g_bsa);
    cudaGetSymbolAddress((void**)&bca, g_bca);
    cudaGetSymbolAddress((void**)&wh, g_wh);
    cudaGetSymbolAddress((void**)&xh, g_xh);
    cudaGetSymbolAddress((void**)&ench, g_ench);
    cudaGetSymbolAddress((void**)&x1h, g_x1h);
    cudaGetSymbolAddress((void**)&x2h, g_x2h);
    cudaGetSymbolAddress((void**)&attnh, g_attnh);
    cudaGetSymbolAddress((void**)&ffh, g_ffh);

    const int PW = DMODEL * DMODEL;
    __half* w_saWqkv = wh + 0 * PW;            // Wq|Wk|Wv contiguous
    __half* w_saWo   = wh + 3 * PW;
    __half* w_caWq   = wh + 4 * PW;
    __half* w_caWkv  = wh + 5 * PW;            // Wk|Wv contiguous
    __half* w_caWo   = wh + 7 * PW;
    __half* w_ffW1   = wh + 8 * PW;
    __half* w_ffW2   = wh + 8 * PW + FFDIM * DMODEL;

    CvtArgs ca;
    const float* srcs[NCVT] = { sa_Wq, sa_Wk, sa_Wv, sa_Wo, ca_Wq, ca_Wk, ca_Wv, ca_Wo,
                                ff_W1, ff_W2, x, enc,
                                sa_bq, sa_bk, sa_bv, ca_bk, ca_bv };
    void* dsts[NCVT] = { w_saWqkv, w_saWqkv + PW, w_saWqkv + 2 * PW, w_saWo,
                         w_caWq, w_caWkv, w_caWkv + PW, w_caWo,
                         w_ffW1, w_ffW2, xh, ench,
                         bsa, bsa + DMODEL, bsa + 2 * DMODEL, bca, bca + DMODEL };
    int ns[NCVT] = { PW, PW, PW, PW, PW, PW, PW, PW,
                     FFDIM * DMODEL, FFDIM * DMODEL, NTOK * DMODEL, NTOK * DMODEL,
                     DMODEL, DMODEL, DMODEL, DMODEL, DMODEL };
    int tof[NCVT] = { 1,1,1,1, 1,1,1,1, 1,1, 1,1, 0,0,0, 0,0 };
    for (int i = 0; i < NCVT; i++) {
        ca.src[i] = srcs[i]; ca.dst[i] = dsts[i]; ca.n4[i] = ns[i] / 4; ca.tof[i] = tof[i];
    }

    cudaFuncSetAttribute(gemm_f16_kernel,
                         cudaFuncAttributeMaxDynamicSharedMemorySize, GEMM_SMEM_BYTES);

    const dim3 gblk(256);
    const dim3 gPair(3 * DMODEL / GBN, NTOK / GBM, 2);   // (12, 32, 2): QKV + cross-KV
    const dim3 gProj(DMODEL / GBN, NTOK / GBM, 1);       // (4, 32) = 128
    const dim3 gProjS2(DMODEL / GBN, NTOK / GBM, 2);     // 256, split-K 2 (K=256/slice)
    const dim3 gFF1(FFDIM / GBN, NTOK / GBM, 1);         // (16, 32) = 512
    const dim3 gFF2S2(DMODEL / GBN, NTOK / GBM, 2);      // 256, split-K 2 (K=1024/slice)
    const dim3 gAttn(S_LEN / AQ_PER_BLOCK, BATCH * NHEAD);  // (16, 16)

    cvt_kernel<<<dim3(128, NCVT), 256>>>(ca);

    // ---- self attention (QKV fused with cross-KV, which only needs enc) ----
    gemm_f16_kernel<<<gPair, gblk, GEMM_SMEM_BYTES>>>(
        xh, w_saWqkv, bsa, qkv, NTOK, 3 * DMODEL, DMODEL, EF_PAIR,
        ench, w_caWkv, bca, kv, 2 * DMODEL);
    attn4_kernel<<<gAttn, 512>>>(qkv, 3 * DMODEL, qkv + DMODEL, qkv + 2 * DMODEL, 3 * DMODEL, attnh);
    gemm_f16_kernel<<<gProjS2, gblk, GEMM_SMEM_BYTES>>>(
        attnh, w_saWo, nullptr, part, NTOK, DMODEL, DMODEL / 2, 0,
        nullptr, nullptr, nullptr, nullptr, 0);
    ln_sum_kernel<<<NTOK, 128>>>(part, 2, sa_bo, x, ln1_g, ln1_b, x1, x1h);

    // ---- cross attention (KV already computed above) ----
    gemm_f16_kernel<<<gProj, gblk, GEMM_SMEM_BYTES>>>(
        x1h, w_caWq, ca_bq, qc, NTOK, DMODEL, DMODEL, 0,
        nullptr, nullptr, nullptr, nullptr, 0);
    attn4_kernel<<<gAttn, 512>>>(qc, DMODEL, kv, kv + DMODEL, 2 * DMODEL, attnh);
    gemm_f16_kernel<<<gProjS2, gblk, GEMM_SMEM_BYTES>>>(
        attnh, w_caWo, nullptr, part, NTOK, DMODEL, DMODEL / 2, 0,
        nullptr, nullptr, nullptr, nullptr, 0);
    ln_sum_kernel<<<NTOK, 128>>>(part, 2, ca_bo, x1, ln2_g, ln2_b, x2, x2h);

    // ---- feed forward ----
    gemm_f16_kernel<<<gFF1, gblk, GEMM_SMEM_BYTES>>>(
        x2h, w_ffW1, ff_b1, (float*)ffh, NTOK, FFDIM, DMODEL, EF_RELU | EF_F16OUT,
        nullptr, nullptr, nullptr, nullptr, 0);
    gemm_f16_kernel<<<gFF2S2, gblk, GEMM_SMEM_BYTES>>>(
        ffh, w_ffW2, nullptr, part, NTOK, DMODEL, FFDIM / 2, 0,
        nullptr, nullptr, nullptr, nullptr, 0);
    ln_sum_kernel<<<NTOK, 128>>>(part, 2, ff_b2, x2, ln3_g, ln3_b, out, nullptr);
}